// round 2
// baseline (speedup 1.0000x reference)
#include <cuda_runtime.h>
#include <cuda_bf16.h>
#include <math.h>

// Problem constants
#define NB     64
#define NOBJ   5
#define CIN    3
#define HI     64
#define WI     96
#define HO     32
#define WO     48
#define NPOS   (HO*WO)          // 1536
#define COUT   128
#define PP     4
#define NT     (NB*NOBJ*NOBJ)   // 1600

#define SIMG_ELEMS (3*65*97)    // 18915 padded image
#define PL_ELEMS   (4*5*NPOS)   // 30720: 4 halves (A0,B0,A1,B1) x 5 images
#define SMEM_FLOATS (SIMG_ELEMS + PL_ELEMS)   // 49635 -> 198540 B

// Channel sums S[t][128] (small static scratch, ~819 KB)
__device__ float g_S[(size_t)NT * COUT];

// ---------------------------------------------------------------------------
// Fused conv + pairwise-combine kernel.
// CTA = (channel-pair g, batch b). Channels c0=2g, c1=2g+1.
// For each of the 5 images of batch b: conv with W_a(c0),W_b(c0),W_a(c1),W_b(c1)
// (weights in registers), planes kept in smem. Then for all 25 (i,j) pairs:
//   S[b*25+i*5+j][c] = sum_pos relu( convA_i + convB_j + bias_c )
// ---------------------------------------------------------------------------
__global__ __launch_bounds__(256, 1)
void fused_kernel(const float* __restrict__ input,   // [320][3][64][96]
                  const float* __restrict__ conv_w,  // [128][6][3][3]
                  const float* __restrict__ conv_b,  // [128]
                  float* __restrict__ S)             // [1600][128]
{
    extern __shared__ float sm[];
    float* simg = sm;               // [3][65][97], zero pad at row 64 / col 96
    float* pl   = sm + SIMG_ELEMS;  // [4][5][1536]

    const int g   = blockIdx.x;     // 0..63
    const int b   = blockIdx.y;     // 0..63
    const int tid = threadIdx.x;
    const int c0  = g * 2, c1 = g * 2 + 1;

    // Load 4 filter halves (27 taps each) into registers. Uniform across
    // threads -> L1/L2 broadcast; done once per CTA.
    float w[4][27];
    #pragma unroll
    for (int t = 0; t < 27; t++) {
        int ic = t / 9, kk = t % 9;
        w[0][t] = conv_w[(c0*6 +     ic)*9 + kk];   // W_a, channel c0
        w[1][t] = conv_w[(c0*6 + 3 + ic)*9 + kk];   // W_b, channel c0
        w[2][t] = conv_w[(c1*6 +     ic)*9 + kk];   // W_a, channel c1
        w[3][t] = conv_w[(c1*6 + 3 + ic)*9 + kk];   // W_b, channel c1
    }
    const float bias0 = conv_b[c0];
    const float bias1 = conv_b[c1];

    // Zero image buffer once; only the pad row/col need to stay zero
    // (data region is overwritten by every image load).
    for (int k = tid; k < SIMG_ELEMS; k += 256) simg[k] = 0.f;

    for (int i = 0; i < 5; i++) {
        __syncthreads();    // previous conv done reading simg (or zero done)
        const float* ib = input + (size_t)(b*NOBJ + i) * (CIN*HI*WI);
        for (int k = tid; k < CIN*HI*WI; k += 256) {
            int c = k / (HI*WI);
            int r = (k / WI) % HI;
            int x = k % WI;
            simg[(c*65 + r)*97 + x] = ib[k];
        }
        __syncthreads();

        // stride-2 SAME conv: out 32x48, iy=2*oy+ky, pad bottom/right only
        #pragma unroll
        for (int pp = 0; pp < 6; pp++) {
            int pos = tid + pp*256;
            int oy = pos / WO, ox = pos % WO;
            int iy = 2*oy,     ix = 2*ox;
            float a0 = 0.f, bv0 = 0.f, a1 = 0.f, bv1 = 0.f;
            #pragma unroll
            for (int c = 0; c < 3; c++) {
                float x9[9];
                const float* p = simg + (c*65 + iy)*97 + ix;
                #pragma unroll
                for (int ky = 0; ky < 3; ky++)
                    #pragma unroll
                    for (int kx = 0; kx < 3; kx++)
                        x9[ky*3 + kx] = p[ky*97 + kx];
                #pragma unroll
                for (int t = 0; t < 9; t++) {
                    a0  = fmaf(w[0][c*9 + t], x9[t], a0);
                    bv0 = fmaf(w[1][c*9 + t], x9[t], bv0);
                    a1  = fmaf(w[2][c*9 + t], x9[t], a1);
                    bv1 = fmaf(w[3][c*9 + t], x9[t], bv1);
                }
            }
            // fold bias into the A-half: v = (a_i + bias) + b_j
            pl[(0*5 + i)*NPOS + pos] = a0 + bias0;
            pl[(1*5 + i)*NPOS + pos] = bv0;
            pl[(2*5 + i)*NPOS + pos] = a1 + bias1;
            pl[(3*5 + i)*NPOS + pos] = bv1;
        }
    }
    __syncthreads();   // all planes visible

    // Combine: per-thread accumulators over this thread's 6 positions.
    float acc0[25], acc1[25];
    #pragma unroll
    for (int q = 0; q < 25; q++) { acc0[q] = 0.f; acc1[q] = 0.f; }

    #pragma unroll
    for (int pp = 0; pp < 6; pp++) {
        int pos = tid + pp*256;
        float A0[5], B0[5], A1[5], B1[5];
        #pragma unroll
        for (int i = 0; i < 5; i++) {
            A0[i] = pl[(0*5 + i)*NPOS + pos];
            B0[i] = pl[(1*5 + i)*NPOS + pos];
            A1[i] = pl[(2*5 + i)*NPOS + pos];
            B1[i] = pl[(3*5 + i)*NPOS + pos];
        }
        #pragma unroll
        for (int i = 0; i < 5; i++)
            #pragma unroll
            for (int j = 0; j < 5; j++) {
                acc0[i*5 + j] += fmaxf(A0[i] + B0[j], 0.f);
                acc1[i*5 + j] += fmaxf(A1[i] + B1[j], 0.f);
            }
    }
    __syncthreads();   // planes area free; reuse as reduction scratch

    // Block reduction: R[50][256] in the plane area.
    float* R = pl;
    #pragma unroll
    for (int q = 0; q < 25; q++) {
        R[(q*2 + 0)*256 + tid] = acc0[q];
        R[(q*2 + 1)*256 + tid] = acc1[q];
    }
    __syncthreads();

    const int lane = tid & 31, wid = tid >> 5;
    for (int o = wid; o < 50; o += 8) {
        float s = 0.f;
        #pragma unroll
        for (int k = 0; k < 8; k++) s += R[o*256 + lane + k*32];
        #pragma unroll
        for (int off = 16; off; off >>= 1)
            s += __shfl_xor_sync(0xFFFFFFFFu, s, off);
        if (lane == 0) {
            int q  = o >> 1;                 // pair index i*5+j
            int ch = (o & 1) ? c1 : c0;
            S[(size_t)(b*25 + q)*COUT + ch] = s;
        }
    }
}

// ---------------------------------------------------------------------------
// logits + sigmoid: preds[t][p] = sigmoid((dot(S[t][p*32:+32], w2[p])/1536 + b2[p]) / temp)
// ---------------------------------------------------------------------------
__global__ void logits_kernel(const float* __restrict__ S,
                              const float* __restrict__ w2,
                              const float* __restrict__ b2,
                              const float* __restrict__ temp,
                              float* __restrict__ out)
{
    int t = blockIdx.x * blockDim.x + threadIdx.x;
    if (t >= NT) return;
    float invT = 1.0f / (*temp);
    #pragma unroll
    for (int p = 0; p < 4; p++) {
        float acc = 0.f;
        #pragma unroll
        for (int cc = 0; cc < 32; cc++)
            acc += S[(size_t)t * COUT + p*32 + cc] * w2[p*32 + cc];
        float logit = acc * (1.0f / (float)NPOS) + b2[p];
        out[t*4 + p] = 1.0f / (1.0f + expf(-logit * invT));
    }
}

// adj[b][t] = (t / 25 == b)
__global__ void adj_kernel(float* __restrict__ out)
{
    int idx = blockIdx.x * blockDim.x + threadIdx.x;
    if (idx >= NB * NT) return;
    int b = idx / NT;
    int t = idx % NT;
    out[idx] = (t / (NOBJ*NOBJ) == b) ? 1.0f : 0.0f;
}

// ---------------------------------------------------------------------------
extern "C" void kernel_launch(void* const* d_in, const int* in_sizes, int n_in,
                              void* d_out, int out_size)
{
    const float* state      = (const float*)d_in[0];
    const float* state_next = (const float*)d_in[1];
    const float* conv_w     = (const float*)d_in[2];
    const float* conv_b     = (const float*)d_in[3];
    const float* w2         = (const float*)d_in[4];
    const float* b2         = (const float*)d_in[5];
    // d_in[6] = n_obj (constant NOBJ, unused)
    const float* temp       = (const float*)d_in[7];
    float* out = (float*)d_out;

    float* S;
    cudaGetSymbolAddress((void**)&S, g_S);

    const size_t fused_smem = (size_t)SMEM_FLOATS * sizeof(float);  // 198540 B
    cudaFuncSetAttribute(fused_kernel, cudaFuncAttributeMaxDynamicSharedMemorySize,
                         (int)fused_smem);

    dim3 grid(64 /*chan pair*/, 64 /*batch*/);

    // state -> preds at out[0]
    fused_kernel<<<grid, 256, fused_smem>>>(state, conv_w, conv_b, S);
    logits_kernel<<<(NT + 255)/256, 256>>>(S, w2, b2, temp, out);

    // state_next -> preds_next at out[6400]
    fused_kernel<<<grid, 256, fused_smem>>>(state_next, conv_w, conv_b, S);
    logits_kernel<<<(NT + 255)/256, 256>>>(S, w2, b2, temp, out + NT*PP);

    // adjacency at out[12800]
    adj_kernel<<<(NB*NT + 255)/256, 256>>>(out + 2*NT*PP);
}

// round 5
// speedup vs baseline: 1.3786x; 1.3786x over previous
#include <cuda_runtime.h>
#include <cuda_bf16.h>
#include <cstdint>
#include <math.h>

// Problem constants
#define NB     64
#define NOBJ   5
#define CIN    3
#define HI     64
#define WI     96
#define HO     32
#define WO     48
#define NPOS   (HO*WO)          // 1536
#define COUT   128
#define PP     4
#define NT     (NB*NOBJ*NOBJ)   // 1600

#define NTHR   384              // 12 warps -> 3 per SMSP
#define NWARP  (NTHR/32)

// Padded image buffer: [3][65][100] floats (stride 100 => 400B rows, 16B aligned)
#define IMG_STRIDE 100
#define IMG_BUF_ELEMS (3*65*IMG_STRIDE)      // 19500 floats = 78000 B
// Planes (bf16): [5 img][1536 pos][4 halves] => 30720 bf16 = 61440 B
#define PL_BF16_ELEMS (5*NPOS*4)
// total dynamic smem: 2 image buffers + planes = 156000 + 61440 = 217440 B
#define SMEM_BYTES (2*IMG_BUF_ELEMS*4 + PL_BF16_ELEMS*2)

__device__ float g_S[(size_t)NT * COUT];     // channel sums S[t][128]

// ---- cp.async helpers -----------------------------------------------------
__device__ __forceinline__ void cp16(uint32_t dst, const void* src) {
    asm volatile("cp.async.cg.shared.global [%0], [%1], 16;\n" :: "r"(dst), "l"(src));
}
__device__ __forceinline__ void cp_commit() {
    asm volatile("cp.async.commit_group;\n");
}
template <int N> __device__ __forceinline__ void cp_wait() {
    asm volatile("cp.async.wait_group %0;\n" :: "n"(N));
}

// Async copy of one image (3x64x96 f32) into a padded smem buffer.
__device__ __forceinline__ void issue_image_copy(uint32_t buf_u32,
                                                 const float* __restrict__ img,
                                                 int tid) {
    // 192 rows x 24 float4 per row = 4608 transfers
    for (int k = tid; k < 192*24; k += NTHR) {
        int row = k / 24, v = k % 24;         // row = c*64 + r
        int c = row >> 6, r = row & 63;
        const float* src = img + row*96 + v*4;
        uint32_t dst = buf_u32 + (uint32_t)(((c*65 + r)*IMG_STRIDE + v*4) * 4);
        cp16(dst, src);
    }
    cp_commit();
}

// ---------------------------------------------------------------------------
// Fused conv + pairwise-combine kernel.
// CTA = (channel-pair g, batch b). Channels c0=2g, c1=2g+1.
// conv(concat(img_i,img_j), W) = conv(img_i, W_a) + conv(img_j, W_b).
// ---------------------------------------------------------------------------
__global__ __launch_bounds__(NTHR, 1)
void fused_kernel(const float* __restrict__ input,   // [320][3][64][96]
                  const float* __restrict__ conv_w,  // [128][6][3][3]
                  const float* __restrict__ conv_b,  // [128]
                  float* __restrict__ S)             // [1600][128]
{
    extern __shared__ float sm[];
    float* buf[2] = { sm, sm + IMG_BUF_ELEMS };
    __nv_bfloat16* pl = (__nv_bfloat16*)(sm + 2*IMG_BUF_ELEMS);
    __shared__ float red[50][NWARP];

    const int g   = blockIdx.x;     // 0..63
    const int b   = blockIdx.y;     // 0..63
    const int tid = threadIdx.x;
    const int c0  = g*2, c1 = g*2 + 1;

    uint32_t buf_u32[2];
    buf_u32[0] = (uint32_t)__cvta_generic_to_shared(buf[0]);
    buf_u32[1] = (uint32_t)__cvta_generic_to_shared(buf[1]);

    // Filter halves in registers (uniform loads -> broadcast)
    float w[4][27];
    #pragma unroll
    for (int t = 0; t < 27; t++) {
        int ic = t / 9, kk = t % 9;
        w[0][t] = conv_w[(c0*6 +     ic)*9 + kk];
        w[1][t] = conv_w[(c0*6 + 3 + ic)*9 + kk];
        w[2][t] = conv_w[(c1*6 +     ic)*9 + kk];
        w[3][t] = conv_w[(c1*6 + 3 + ic)*9 + kk];
    }
    const float bias0 = conv_b[c0];
    const float bias1 = conv_b[c1];

    // Zero both buffers once (SAME zero-padding at row 64 / cols 96..99).
    for (int k = tid; k < 2*IMG_BUF_ELEMS; k += NTHR) sm[k] = 0.f;
    __syncthreads();

    const float* imgs = input + (size_t)b * NOBJ * (CIN*HI*WI);

    // Prime pipeline: images 0 and 1 in flight.
    issue_image_copy(buf_u32[0], imgs + 0*(CIN*HI*WI), tid);
    issue_image_copy(buf_u32[1], imgs + 1*(CIN*HI*WI), tid);

    for (int i = 0; i < 5; i++) {
        if (i < 4) cp_wait<1>(); else cp_wait<0>();
        __syncthreads();                     // image i fully in buf[i&1]

        const float* sb = buf[i & 1];
        #pragma unroll
        for (int pp = 0; pp < 4; pp++) {
            int pos = tid + pp*NTHR;         // 4*384 = 1536
            int oy = pos / WO, ox = pos % WO;
            int iy = 2*oy,     ix = 2*ox;
            float a0 = 0.f, b0v = 0.f, a1 = 0.f, b1v = 0.f;
            #pragma unroll
            for (int c = 0; c < 3; c++) {
                float x9[9];
                const float* p = sb + (c*65 + iy)*IMG_STRIDE + ix;
                #pragma unroll
                for (int ky = 0; ky < 3; ky++)
                    #pragma unroll
                    for (int kx = 0; kx < 3; kx++)
                        x9[ky*3 + kx] = p[ky*IMG_STRIDE + kx];
                #pragma unroll
                for (int t = 0; t < 9; t++) {
                    a0  = fmaf(w[0][c*9 + t], x9[t], a0);
                    b0v = fmaf(w[1][c*9 + t], x9[t], b0v);
                    a1  = fmaf(w[2][c*9 + t], x9[t], a1);
                    b1v = fmaf(w[3][c*9 + t], x9[t], b1v);
                }
            }
            // pack 4 halves as bf16x4 (A0,B0,A1,B1); bias folded into A halves
            union { __nv_bfloat162 h2[2]; uint2 u; } cv;
            cv.h2[0] = __floats2bfloat162_rn(a0 + bias0, b0v);
            cv.h2[1] = __floats2bfloat162_rn(a1 + bias1, b1v);
            *(uint2*)(pl + ((size_t)i*NPOS + pos)*4) = cv.u;
        }
        __syncthreads();                     // conv i done reading buf[i&1]
        if (i < 3)                           // prefetch image i+2 into buf[i&1]
            issue_image_copy(buf_u32[i & 1], imgs + (i+2)*(CIN*HI*WI), tid);
    }
    __syncthreads();                         // all planes visible

    // Combine: 25 pairs x 2 channels, per-thread accumulation over 4 positions
    float acc0[25], acc1[25];
    #pragma unroll
    for (int q = 0; q < 25; q++) { acc0[q] = 0.f; acc1[q] = 0.f; }

    #pragma unroll
    for (int pp = 0; pp < 4; pp++) {
        int pos = tid + pp*NTHR;
        float A0[5], B0[5], A1[5], B1[5];
        #pragma unroll
        for (int i = 0; i < 5; i++) {
            uint2 u = *(const uint2*)(pl + ((size_t)i*NPOS + pos)*4);
            float2 f01 = __bfloat1622float2(*(__nv_bfloat162*)&u.x);
            float2 f23 = __bfloat1622float2(*(__nv_bfloat162*)&u.y);
            A0[i] = f01.x; B0[i] = f01.y;
            A1[i] = f23.x; B1[i] = f23.y;
        }
        #pragma unroll
        for (int i = 0; i < 5; i++)
            #pragma unroll
            for (int j = 0; j < 5; j++) {
                acc0[i*5 + j] += fmaxf(A0[i] + B0[j], 0.f);
                acc1[i*5 + j] += fmaxf(A1[i] + B1[j], 0.f);
            }
    }

    // Shuffle-first reduction: warp-reduce each of the 50 accumulators.
    const int lane = tid & 31, wid = tid >> 5;
    #pragma unroll
    for (int q = 0; q < 25; q++) {
        float s0 = acc0[q], s1 = acc1[q];
        #pragma unroll
        for (int off = 16; off; off >>= 1) {
            s0 += __shfl_xor_sync(0xFFFFFFFFu, s0, off);
            s1 += __shfl_xor_sync(0xFFFFFFFFu, s1, off);
        }
        if (lane == 0) {
            red[q*2 + 0][wid] = s0;
            red[q*2 + 1][wid] = s1;
        }
    }
    __syncthreads();

    if (tid < 50) {
        float s = 0.f;
        #pragma unroll
        for (int k = 0; k < NWARP; k++) s += red[tid][k];
        int q  = tid >> 1;
        int ch = (tid & 1) ? c1 : c0;
        S[(size_t)(b*25 + q)*COUT + ch] = s;
    }
}

// ---------------------------------------------------------------------------
// logits: warp per tuple, coalesced S reads, shuffle reduce.
// ---------------------------------------------------------------------------
__global__ __launch_bounds__(256)
void logits_kernel(const float* __restrict__ S,
                   const float* __restrict__ w2,    // [4][32]
                   const float* __restrict__ b2,    // [4]
                   const float* __restrict__ temp,
                   float* __restrict__ out)         // [1600][4]
{
    const int lane = threadIdx.x & 31;
    const int t = blockIdx.x * 8 + (threadIdx.x >> 5);
    if (t >= NT) return;

    float s[4];
    #pragma unroll
    for (int p = 0; p < 4; p++)
        s[p] = S[(size_t)t*COUT + p*32 + lane] * w2[p*32 + lane];
    #pragma unroll
    for (int off = 16; off; off >>= 1)
        #pragma unroll
        for (int p = 0; p < 4; p++)
            s[p] += __shfl_xor_sync(0xFFFFFFFFu, s[p], off);

    if (lane < 4) {
        float invT = 1.0f / (*temp);
        float logit = s[lane] * (1.0f / (float)NPOS) + b2[lane];
        out[t*4 + lane] = 1.0f / (1.0f + expf(-logit * invT));
    }
}

// adj[b][t] = (t / 25 == b)
__global__ void adj_kernel(float* __restrict__ out)
{
    int idx = blockIdx.x * blockDim.x + threadIdx.x;
    if (idx >= NB * NT) return;
    int b = idx / NT;
    int t = idx % NT;
    out[idx] = (t / (NOBJ*NOBJ) == b) ? 1.0f : 0.0f;
}

// ---------------------------------------------------------------------------
extern "C" void kernel_launch(void* const* d_in, const int* in_sizes, int n_in,
                              void* d_out, int out_size)
{
    const float* state      = (const float*)d_in[0];
    const float* state_next = (const float*)d_in[1];
    const float* conv_w     = (const float*)d_in[2];
    const float* conv_b     = (const float*)d_in[3];
    const float* w2         = (const float*)d_in[4];
    const float* b2         = (const float*)d_in[5];
    // d_in[6] = n_obj (constant NOBJ), d_in[7] = temp
    const float* temp       = (const float*)d_in[7];
    float* out = (float*)d_out;

    float* S;
    cudaGetSymbolAddress((void**)&S, g_S);

    cudaFuncSetAttribute(fused_kernel, cudaFuncAttributeMaxDynamicSharedMemorySize,
                         SMEM_BYTES);

    dim3 grid(64 /*chan pair*/, 64 /*batch*/);

    fused_kernel<<<grid, NTHR, SMEM_BYTES>>>(state, conv_w, conv_b, S);
    logits_kernel<<<200, 256>>>(S, w2, b2, temp, out);                 // preds

    fused_kernel<<<grid, NTHR, SMEM_BYTES>>>(state_next, conv_w, conv_b, S);
    logits_kernel<<<200, 256>>>(S, w2, b2, temp, out + NT*PP);         // preds_next

    adj_kernel<<<(NB*NT + 255)/256, 256>>>(out + 2*NT*PP);             // adj
}

// round 6
// speedup vs baseline: 1.8942x; 1.3740x over previous
#include <cuda_runtime.h>
#include <cuda_bf16.h>
#include <cstdint>
#include <math.h>

// Problem constants
#define NB     64
#define NOBJ   5
#define CIN    3
#define HI     64
#define WI     96
#define HO     32
#define WO     48
#define NPOS   (HO*WO)          // 1536
#define COUT   128
#define PP     4
#define NT     (NB*NOBJ*NOBJ)   // 1600

#define NTHR   384              // 12 warps -> 3 per SMSP; 384 = 16x24 2x2-blocks
#define NWARP  (NTHR/32)

// Padded image buffer: [3][65][100] floats (stride 100 => 400B rows, 16B aligned)
#define IMG_STRIDE 100
#define IMG_BUF_ELEMS (3*65*IMG_STRIDE)      // 19500 floats = 78000 B
// Planes (bf16): [5 img][1536 pos][4 halves] => 30720 bf16 = 61440 B
#define PL_BF16_ELEMS (5*NPOS*4)
// total dynamic smem: 2 image buffers + planes = 156000 + 61440 = 217440 B
#define SMEM_BYTES (2*IMG_BUF_ELEMS*4 + PL_BF16_ELEMS*2)

__device__ float g_S[(size_t)NT * COUT];     // channel sums S[t][128]

// ---- cp.async helpers -----------------------------------------------------
__device__ __forceinline__ void cp16(uint32_t dst, const void* src) {
    asm volatile("cp.async.cg.shared.global [%0], [%1], 16;\n" :: "r"(dst), "l"(src));
}
__device__ __forceinline__ void cp_commit() {
    asm volatile("cp.async.commit_group;\n");
}
template <int N> __device__ __forceinline__ void cp_wait() {
    asm volatile("cp.async.wait_group %0;\n" :: "n"(N));
}

// Async copy of one image (3x64x96 f32) into a padded smem buffer.
__device__ __forceinline__ void issue_image_copy(uint32_t buf_u32,
                                                 const float* __restrict__ img,
                                                 int tid) {
    // 192 rows x 24 float4 per row = 4608 transfers
    for (int k = tid; k < 192*24; k += NTHR) {
        int row = k / 24, v = k % 24;         // row = c*64 + r
        int c = row >> 6, r = row & 63;
        const float* src = img + row*96 + v*4;
        uint32_t dst = buf_u32 + (uint32_t)(((c*65 + r)*IMG_STRIDE + v*4) * 4);
        cp16(dst, src);
    }
    cp_commit();
}

// ---------------------------------------------------------------------------
// Fused conv + pairwise-combine kernel.
// CTA = (channel-pair g, batch b). Channels c0=2g, c1=2g+1.
// conv(concat(img_i,img_j), W) = conv(img_i, W_a) + conv(img_j, W_b).
// Each thread computes a 2x2 output block -> conflict-free LDS.128 patch loads
// and 16 independent FFMA accumulation chains.
// ---------------------------------------------------------------------------
__global__ __launch_bounds__(NTHR, 1)
void fused_kernel(const float* __restrict__ input,   // [320][3][64][96]
                  const float* __restrict__ conv_w,  // [128][6][3][3]
                  const float* __restrict__ conv_b,  // [128]
                  float* __restrict__ S)             // [1600][128]
{
    extern __shared__ float sm[];
    float* buf[2] = { sm, sm + IMG_BUF_ELEMS };
    __nv_bfloat16* pl = (__nv_bfloat16*)(sm + 2*IMG_BUF_ELEMS);
    __shared__ float red[50][NWARP];

    const int g   = blockIdx.x;     // 0..63
    const int b   = blockIdx.y;     // 0..63
    const int tid = threadIdx.x;
    const int c0  = g*2, c1 = g*2 + 1;

    uint32_t buf_u32[2];
    buf_u32[0] = (uint32_t)__cvta_generic_to_shared(buf[0]);
    buf_u32[1] = (uint32_t)__cvta_generic_to_shared(buf[1]);

    // Filter halves in registers (uniform loads -> broadcast)
    // f index: 0 = W_a(c0), 1 = W_b(c0), 2 = W_a(c1), 3 = W_b(c1)
    float w[4][27];
    #pragma unroll
    for (int t = 0; t < 27; t++) {
        int ic = t / 9, kk = t % 9;
        w[0][t] = conv_w[(c0*6 +     ic)*9 + kk];
        w[1][t] = conv_w[(c0*6 + 3 + ic)*9 + kk];
        w[2][t] = conv_w[(c1*6 +     ic)*9 + kk];
        w[3][t] = conv_w[(c1*6 + 3 + ic)*9 + kk];
    }
    const float bias0 = conv_b[c0];
    const float bias1 = conv_b[c1];

    // Zero both buffers once (SAME zero-padding at row 64 / cols 96..99).
    for (int k = tid; k < 2*IMG_BUF_ELEMS; k += NTHR) sm[k] = 0.f;
    __syncthreads();

    const float* imgs = input + (size_t)b * NOBJ * (CIN*HI*WI);

    // Prime pipeline: images 0 and 1 in flight.
    issue_image_copy(buf_u32[0], imgs + 0*(CIN*HI*WI), tid);
    issue_image_copy(buf_u32[1], imgs + 1*(CIN*HI*WI), tid);

    // 2x2 output block coords: 16 x 24 blocks = 384 threads, one block each.
    const int by = tid / 24, bx = tid % 24;
    const int iy = 4*by,     ix = 4*bx;      // top-left input coords
    const int pos_tl = (2*by)*WO + 2*bx;

    for (int i = 0; i < 5; i++) {
        if (i < 4) cp_wait<1>(); else cp_wait<0>();
        __syncthreads();                     // image i fully in buf[i&1]

        const float* sb = buf[i & 1];

        // acc[f][p]: f = filter half (A0,B0,A1,B1), p = pos (tl,tr,bl,br)
        float acc[4][4];
        #pragma unroll
        for (int f = 0; f < 4; f++)
            #pragma unroll
            for (int p = 0; p < 4; p++) acc[f][p] = 0.f;

        #pragma unroll
        for (int c = 0; c < 3; c++) {
            #pragma unroll
            for (int r = 0; r < 5; r++) {
                const float* rp = sb + (c*65 + iy + r)*IMG_STRIDE + ix;
                float4 v4 = *(const float4*)rp;      // cols ix..ix+3 (16B aligned)
                float v[5] = { v4.x, v4.y, v4.z, v4.w, rp[4] };

                if (r < 3) {                          // top row pair, ky = r
                    #pragma unroll
                    for (int kx = 0; kx < 3; kx++) {
                        int t = c*9 + r*3 + kx;
                        #pragma unroll
                        for (int f = 0; f < 4; f++) {
                            acc[f][0] = fmaf(w[f][t], v[kx],   acc[f][0]); // tl
                            acc[f][1] = fmaf(w[f][t], v[kx+2], acc[f][1]); // tr
                        }
                    }
                }
                if (r >= 2) {                         // bottom row pair, ky = r-2
                    #pragma unroll
                    for (int kx = 0; kx < 3; kx++) {
                        int t = c*9 + (r-2)*3 + kx;
                        #pragma unroll
                        for (int f = 0; f < 4; f++) {
                            acc[f][2] = fmaf(w[f][t], v[kx],   acc[f][2]); // bl
                            acc[f][3] = fmaf(w[f][t], v[kx+2], acc[f][3]); // br
                        }
                    }
                }
            }
        }

        // Store 4 positions, packed bf16x4 (A0,B0,A1,B1); bias folded into A.
        const int poss[4] = { pos_tl, pos_tl + 1, pos_tl + WO, pos_tl + WO + 1 };
        #pragma unroll
        for (int p = 0; p < 4; p++) {
            union { __nv_bfloat162 h2[2]; uint2 u; } cv;
            cv.h2[0] = __floats2bfloat162_rn(acc[0][p] + bias0, acc[1][p]);
            cv.h2[1] = __floats2bfloat162_rn(acc[2][p] + bias1, acc[3][p]);
            *(uint2*)(pl + ((size_t)i*NPOS + poss[p])*4) = cv.u;
        }

        __syncthreads();                     // conv i done reading buf[i&1]
        if (i < 3)                           // prefetch image i+2 into buf[i&1]
            issue_image_copy(buf_u32[i & 1], imgs + (i+2)*(CIN*HI*WI), tid);
    }
    __syncthreads();                         // all planes visible

    // Combine: 25 pairs x 2 channels, per-thread accumulation over 4 positions
    float acc0[25], acc1[25];
    #pragma unroll
    for (int q = 0; q < 25; q++) { acc0[q] = 0.f; acc1[q] = 0.f; }

    #pragma unroll
    for (int pp = 0; pp < 4; pp++) {
        int pos = tid + pp*NTHR;
        float A0[5], B0[5], A1[5], B1[5];
        #pragma unroll
        for (int i = 0; i < 5; i++) {
            uint2 u = *(const uint2*)(pl + ((size_t)i*NPOS + pos)*4);
            float2 f01 = __bfloat1622float2(*(__nv_bfloat162*)&u.x);
            float2 f23 = __bfloat1622float2(*(__nv_bfloat162*)&u.y);
            A0[i] = f01.x; B0[i] = f01.y;
            A1[i] = f23.x; B1[i] = f23.y;
        }
        #pragma unroll
        for (int i = 0; i < 5; i++)
            #pragma unroll
            for (int j = 0; j < 5; j++) {
                acc0[i*5 + j] += fmaxf(A0[i] + B0[j], 0.f);
                acc1[i*5 + j] += fmaxf(A1[i] + B1[j], 0.f);
            }
    }

    // Shuffle-first reduction: warp-reduce each of the 50 accumulators.
    const int lane = tid & 31, wid = tid >> 5;
    #pragma unroll
    for (int q = 0; q < 25; q++) {
        float s0 = acc0[q], s1 = acc1[q];
        #pragma unroll
        for (int off = 16; off; off >>= 1) {
            s0 += __shfl_xor_sync(0xFFFFFFFFu, s0, off);
            s1 += __shfl_xor_sync(0xFFFFFFFFu, s1, off);
        }
        if (lane == 0) {
            red[q*2 + 0][wid] = s0;
            red[q*2 + 1][wid] = s1;
        }
    }
    __syncthreads();

    if (tid < 50) {
        float s = 0.f;
        #pragma unroll
        for (int k = 0; k < NWARP; k++) s += red[tid][k];
        int q  = tid >> 1;
        int ch = (tid & 1) ? c1 : c0;
        S[(size_t)(b*25 + q)*COUT + ch] = s;
    }
}

// ---------------------------------------------------------------------------
// logits: warp per tuple, coalesced S reads, shuffle reduce.
// ---------------------------------------------------------------------------
__global__ __launch_bounds__(256)
void logits_kernel(const float* __restrict__ S,
                   const float* __restrict__ w2,    // [4][32]
                   const float* __restrict__ b2,    // [4]
                   const float* __restrict__ temp,
                   float* __restrict__ out)         // [1600][4]
{
    const int lane = threadIdx.x & 31;
    const int t = blockIdx.x * 8 + (threadIdx.x >> 5);
    if (t >= NT) return;

    float s[4];
    #pragma unroll
    for (int p = 0; p < 4; p++)
        s[p] = S[(size_t)t*COUT + p*32 + lane] * w2[p*32 + lane];
    #pragma unroll
    for (int off = 16; off; off >>= 1)
        #pragma unroll
        for (int p = 0; p < 4; p++)
            s[p] += __shfl_xor_sync(0xFFFFFFFFu, s[p], off);

    if (lane < 4) {
        float invT = 1.0f / (*temp);
        float logit = s[lane] * (1.0f / (float)NPOS) + b2[lane];
        out[t*4 + lane] = 1.0f / (1.0f + expf(-logit * invT));
    }
}

// adj[b][t] = (t / 25 == b)
__global__ void adj_kernel(float* __restrict__ out)
{
    int idx = blockIdx.x * blockDim.x + threadIdx.x;
    if (idx >= NB * NT) return;
    int b = idx / NT;
    int t = idx % NT;
    out[idx] = (t / (NOBJ*NOBJ) == b) ? 1.0f : 0.0f;
}

// ---------------------------------------------------------------------------
extern "C" void kernel_launch(void* const* d_in, const int* in_sizes, int n_in,
                              void* d_out, int out_size)
{
    const float* state      = (const float*)d_in[0];
    const float* state_next = (const float*)d_in[1];
    const float* conv_w     = (const float*)d_in[2];
    const float* conv_b     = (const float*)d_in[3];
    const float* w2         = (const float*)d_in[4];
    const float* b2         = (const float*)d_in[5];
    // d_in[6] = n_obj (constant NOBJ), d_in[7] = temp
    const float* temp       = (const float*)d_in[7];
    float* out = (float*)d_out;

    float* S;
    cudaGetSymbolAddress((void**)&S, g_S);

    cudaFuncSetAttribute(fused_kernel, cudaFuncAttributeMaxDynamicSharedMemorySize,
                         SMEM_BYTES);

    dim3 grid(64 /*chan pair*/, 64 /*batch*/);

    fused_kernel<<<grid, NTHR, SMEM_BYTES>>>(state, conv_w, conv_b, S);
    logits_kernel<<<200, 256>>>(S, w2, b2, temp, out);                 // preds

    fused_kernel<<<grid, NTHR, SMEM_BYTES>>>(state_next, conv_w, conv_b, S);
    logits_kernel<<<200, 256>>>(S, w2, b2, temp, out + NT*PP);         // preds_next

    adj_kernel<<<(NB*NT + 255)/256, 256>>>(out + 2*NT*PP);             // adj
}